// round 1
// baseline (speedup 1.0000x reference)
#include <cuda_runtime.h>

// DigitCaps fused kernel for GB300 (sm_103a).
//
// Algebraic restructuring:
//   output[b,c] = (sum_n u[b,n,:]) . dc_new[c,:] / N      (no sims_final pass)
//   dc_new      = dc + (seg_u - counts*dc) / (B*N)
// So one streaming pass over inputs computes: sum_u[128][8], seg_u[10][8], counts[10].
// A tiny finalize kernel produces output [128,10] and dc_new [10,8].

#define Bsz    128
#define Jtot   4608
#define Cc     10
#define Dd     8
#define Mm     4
#define Ntot   (Jtot * Mm)          // 18432

#define JB     32                   // j-tile per block
#define BB     32                   // b-tile per block
#define NTHR   256
#define NSLOTS 90                   // 80 seg (c*8+d) + 10 counts

// scratch: [0,1024) sum_u[b][d]; [1024,1104) seg[c*8+d]; [1104,1114) cnt[c]
__device__ float g_scratch[1120];

__global__ void init_scratch_kernel() {
    int i = blockIdx.x * blockDim.x + threadIdx.x;
    if (i < 1120) g_scratch[i] = 0.0f;
}

extern __shared__ float smem[];

__global__ __launch_bounds__(NTHR, 1)
void caps_main_kernel(const float* __restrict__ xin,   // [B, J, 8]
                      const float* __restrict__ Wg,    // [J, 8, 32]
                      const float* __restrict__ dcg)   // [10, 8]
{
    float* sW   = smem;                       // JB*256   = 8192 floats
    float* sX   = sW + JB * 256;              // BB*JB*8  = 8192 floats
    float* sSeg = sX + BB * JB * 8;           // NSLOTS*256 = 23040 floats

    const int tid = threadIdx.x;
    const int j0  = blockIdx.x * JB;
    const int b0  = blockIdx.y * BB;

    // ---- stage W tile: rows j0..j0+JB-1, each 256 contiguous floats ----
    {
        const float4* src = (const float4*)(Wg + (size_t)j0 * 256);
        float4* dst = (float4*)sW;
        #pragma unroll 4
        for (int i = tid; i < JB * 64; i += NTHR) dst[i] = src[i];
    }
    // ---- stage X tile: [bl][jl][i], contiguous per bl in source ----
    {
        float4* dst = (float4*)sX;
        for (int i = tid; i < BB * 64; i += NTHR) {
            int bl = i >> 6;
            int r  = i & 63;
            const float4* src =
                (const float4*)(xin + (size_t)(b0 + bl) * (Jtot * 8) + (size_t)j0 * 8);
            dst[i] = src[r];
        }
    }
    // ---- zero private seg columns ----
    for (int i = tid; i < NSLOTS * 256; i += NTHR) sSeg[i] = 0.0f;

    // ---- digit_caps in registers (fully unrolled use below) ----
    float rdc[Cc * Dd];
    #pragma unroll
    for (int i = 0; i < Cc * Dd; i++) rdc[i] = __ldg(dcg + i);

    __syncthreads();

    const int bl  = tid >> 3;       // fixed batch row per thread
    const int sub = tid & 7;
    const int b   = b0 + bl;

    float su[Dd];
    #pragma unroll
    for (int d = 0; d < Dd; d++) su[d] = 0.0f;

    const float* xrow = sX + bl * (JB * 8);

    for (int it = 0; it < (JB * Mm) / 8; ++it) {   // 16 items per thread
        int p  = it * 8 + sub;
        int jl = p >> 2;
        int m  = p & 3;

        const float*  xs = xrow + jl * 8;
        const float4* w4 = (const float4*)(sW + jl * 256) + m * 2;

        float u[Dd];
        #pragma unroll
        for (int d = 0; d < Dd; d++) u[d] = 0.0f;

        #pragma unroll
        for (int i = 0; i < 8; i++) {
            float  xv = xs[i];
            float4 a  = w4[i * 8];
            float4 c4 = w4[i * 8 + 1];
            u[0] += xv * a.x;  u[1] += xv * a.y;
            u[2] += xv * a.z;  u[3] += xv * a.w;
            u[4] += xv * c4.x; u[5] += xv * c4.y;
            u[6] += xv * c4.z; u[7] += xv * c4.w;
        }

        #pragma unroll
        for (int d = 0; d < Dd; d++) su[d] += u[d];

        // argmax over classes (first-max semantics like jnp.argmax)
        float best;
        int   wbest = 0;
        {
            float s = 0.0f;
            #pragma unroll
            for (int d = 0; d < Dd; d++) s += u[d] * rdc[d];
            best = s;
        }
        #pragma unroll
        for (int c = 1; c < Cc; c++) {
            float s = 0.0f;
            #pragma unroll
            for (int d = 0; d < Dd; d++) s += u[d] * rdc[c * 8 + d];
            if (s > best) { best = s; wbest = c; }
        }

        // per-thread-private segment accumulation (conflict-free: bank = tid%32)
        float* segp = sSeg + (wbest * 8) * 256 + tid;
        #pragma unroll
        for (int d = 0; d < Dd; d++) segp[d * 256] += u[d];
        sSeg[(80 + wbest) * 256 + tid] += 1.0f;
    }

    // ---- sum_u: reduce over the 8 threads sharing b, then one atomic each ----
    #pragma unroll
    for (int d = 0; d < Dd; d++) {
        float v = su[d];
        v += __shfl_xor_sync(0xffffffffu, v, 1);
        v += __shfl_xor_sync(0xffffffffu, v, 2);
        v += __shfl_xor_sync(0xffffffffu, v, 4);
        su[d] = v;
    }
    if (sub == 0) {
        #pragma unroll
        for (int d = 0; d < Dd; d++) atomicAdd(&g_scratch[b * 8 + d], su[d]);
    }

    __syncthreads();

    // ---- reduce the 90 private-column slots; warp per slot, conflict-free ----
    const int warp = tid >> 5;
    const int lane = tid & 31;
    for (int slot = warp; slot < NSLOTS; slot += 8) {
        const float* base = sSeg + slot * 256;
        float acc = 0.0f;
        #pragma unroll
        for (int k = 0; k < 8; k++) acc += base[k * 32 + lane];
        acc += __shfl_xor_sync(0xffffffffu, acc, 16);
        acc += __shfl_xor_sync(0xffffffffu, acc, 8);
        acc += __shfl_xor_sync(0xffffffffu, acc, 4);
        acc += __shfl_xor_sync(0xffffffffu, acc, 2);
        acc += __shfl_xor_sync(0xffffffffu, acc, 1);
        if (lane == 0) atomicAdd(&g_scratch[1024 + slot], acc);
    }
}

__global__ void caps_final_kernel(const float* __restrict__ dcg,
                                  float* __restrict__ out)
{
    __shared__ float dcn[Cc * Dd];
    const int tid = threadIdx.x;   // 256 threads, 1 block

    if (tid < Cc * Dd) {
        int   c   = tid >> 3;
        float v   = dcg[tid];
        float upd = (g_scratch[1024 + tid] - g_scratch[1104 + c] * v)
                    * (1.0f / (float)(Bsz * Ntot));
        float nv  = v + upd;
        dcn[tid] = nv;
        out[Bsz * Cc + tid] = nv;          // digit_caps_new tail
    }
    __syncthreads();

    for (int idx = tid; idx < Bsz * Cc; idx += blockDim.x) {
        int b = idx / Cc;
        int c = idx - b * Cc;
        float s = 0.0f;
        #pragma unroll
        for (int d = 0; d < Dd; d++) s += g_scratch[b * 8 + d] * dcn[c * 8 + d];
        out[idx] = s * (1.0f / (float)Ntot);
    }
}

extern "C" void kernel_launch(void* const* d_in, const int* in_sizes, int n_in,
                              void* d_out, int out_size)
{
    const float* xin = (const float*)d_in[0];  // inputs [128,12,12,32,8]
    const float* Wg  = (const float*)d_in[1];  // W [4608,8,32]
    const float* dcg = (const float*)d_in[2];  // digit_caps [10,8]
    float* out = (float*)d_out;

    init_scratch_kernel<<<5, 256>>>();

    size_t smemBytes = (size_t)(JB * 256 + BB * JB * 8 + NSLOTS * 256) * sizeof(float);
    cudaFuncSetAttribute(caps_main_kernel,
                         cudaFuncAttributeMaxDynamicSharedMemorySize,
                         (int)smemBytes);
    dim3 grid(Jtot / JB, Bsz / BB);
    caps_main_kernel<<<grid, NTHR, smemBytes>>>(xin, Wg, dcg);

    caps_final_kernel<<<1, 256>>>(dcg, out);
}

// round 3
// speedup vs baseline: 1.5934x; 1.5934x over previous
#include <cuda_runtime.h>
#include <cuda_bf16.h>

// DigitCaps fused kernel for GB300 (sm_103a), round 3 (r2 + cvt fix).
//
//   output[b,c] = (sum_n u[b,n,:]) . dc_new[c,:] / N
//   dc_new      = dc + (seg_u - counts*dc) / (B*N)
// One streaming pass computes sum_u[128][8], seg_u[10][8], counts[10];
// a tiny finalize kernel produces the outputs and re-zeroes the scratch.

#define Bsz    128
#define Jtot   4608
#define Cc     10
#define Dd     8
#define Mm     4
#define Ntot   (Jtot * Mm)          // 18432

#define JB     32
#define BB     32
#define NTHR   256
#define WSTR   260                  // padded W row stride (floats): conflict-free
#define XSTR   258                  // padded X row stride (floats): conflict-free
#define NPAIR  45                   // 40 seg bf16x2 pairs + 5 count pairs

// scratch: [0,1024) sum_u[b][d]; [1024,1104) seg[c*8+d]; [1104,1114) cnt[c]
// zero at module load; caps_final re-zeroes after consuming -> no init kernel.
__device__ float g_scratch[1120];

// ---- packed f32x2 helpers (ptxas never emits FFMA2 from C++) ----
__device__ __forceinline__ unsigned long long pk2(float lo, float hi) {
    unsigned long long r;
    asm("mov.b64 %0, {%1, %2};" : "=l"(r) : "f"(lo), "f"(hi));
    return r;
}
__device__ __forceinline__ float2 upk2(unsigned long long a) {
    float2 r;
    asm("mov.b64 {%0, %1}, %2;" : "=f"(r.x), "=f"(r.y) : "l"(a));
    return r;
}
__device__ __forceinline__ unsigned long long fma2(unsigned long long a,
                                                   unsigned long long b,
                                                   unsigned long long c) {
    unsigned long long d;
    asm("fma.rn.f32x2 %0, %1, %2, %3;" : "=l"(d) : "l"(a), "l"(b), "l"(c));
    return d;
}
__device__ __forceinline__ unsigned long long mul2(unsigned long long a,
                                                   unsigned long long b) {
    unsigned long long d;
    asm("mul.rn.f32x2 %0, %1, %2;" : "=l"(d) : "l"(a), "l"(b));
    return d;
}
__device__ __forceinline__ unsigned long long add2(unsigned long long a,
                                                   unsigned long long b) {
    unsigned long long d;
    asm("add.rn.f32x2 %0, %1, %2;" : "=l"(d) : "l"(a), "l"(b));
    return d;
}
// pack-to-bf16x2: lo float -> bits[15:0], hi float -> bits[31:16]
__device__ __forceinline__ unsigned cvt_bf16x2(unsigned long long p) {
    float2 t = upk2(p);
    unsigned r;
    asm("cvt.rn.bf16x2.f32 %0, %1, %2;" : "=r"(r) : "f"(t.y), "f"(t.x));
    return r;
}

extern __shared__ float smem[];

__global__ __launch_bounds__(NTHR, 2)
void caps_main_kernel(const float* __restrict__ xin,   // [B, J, 8]
                      const float* __restrict__ Wg,    // [J, 8, 32]
                      const float* __restrict__ dcg)   // [10, 8]
{
    float*    sW   = smem;                               // JB*WSTR = 8320 f
    float*    sX   = sW + JB * WSTR;                     // BB*XSTR = 8256 f
    unsigned* sSeg = (unsigned*)(sX + BB * XSTR);        // NPAIR*256 = 11520 u32

    const int tid = threadIdx.x;
    const int j0  = blockIdx.x * JB;
    const int b0  = blockIdx.y * BB;

    // ---- stage W tile (padded rows, float4) ----
    {
        const float4* src = (const float4*)(Wg + (size_t)j0 * 256);
        #pragma unroll 4
        for (int i = tid; i < JB * 64; i += NTHR) {
            int jl = i >> 6, r = i & 63;
            ((float4*)sW)[jl * (WSTR / 4) + r] = src[i];
        }
    }
    // ---- stage X tile (padded rows, float2: XSTR is not /4) ----
    {
        for (int i = tid; i < BB * 128; i += NTHR) {
            int bl = i >> 7, r = i & 127;
            const float2* src =
                (const float2*)(xin + (size_t)(b0 + bl) * (Jtot * 8) + (size_t)j0 * 8);
            ((float2*)sX)[bl * (XSTR / 2) + r] = src[r];
        }
    }
    // ---- zero private seg columns ----
    for (int i = tid; i < NPAIR * 256; i += NTHR) sSeg[i] = 0u;

    // ---- digit_caps as 40 f32x2 pairs in registers ----
    unsigned long long rdc[Cc * 4];
    #pragma unroll
    for (int i = 0; i < Cc * 4; i++) {
        float2 v = ((const float2*)dcg)[i];
        rdc[i] = pk2(v.x, v.y);
    }

    __syncthreads();

    const int bl  = tid >> 3;
    const int sub = tid & 7;
    const int b   = b0 + bl;

    unsigned long long su0 = 0, su1 = 0, su2 = 0, su3 = 0;
    const float2* xrow = (const float2*)sX + bl * (XSTR / 2);

    for (int it = 0; it < 16; ++it) {
        const int p  = it * 8 + sub;
        const int jl = p >> 2;
        const int m  = p & 3;

        const float2* xs = xrow + jl * 4;
        const float4* w4 = (const float4*)sW + jl * (WSTR / 4) + m * 2;

        unsigned long long u0 = 0, u1 = 0, u2 = 0, u3 = 0;
        #pragma unroll
        for (int k = 0; k < 4; k++) {
            float2 xp = xs[k];
            unsigned long long xa = pk2(xp.x, xp.x);
            unsigned long long xb = pk2(xp.y, xp.y);
            float4 wA = w4[(2 * k) * 8];
            float4 wB = w4[(2 * k) * 8 + 1];
            u0 = fma2(xa, pk2(wA.x, wA.y), u0);
            u1 = fma2(xa, pk2(wA.z, wA.w), u1);
            u2 = fma2(xa, pk2(wB.x, wB.y), u2);
            u3 = fma2(xa, pk2(wB.z, wB.w), u3);
            float4 wC = w4[(2 * k + 1) * 8];
            float4 wD = w4[(2 * k + 1) * 8 + 1];
            u0 = fma2(xb, pk2(wC.x, wC.y), u0);
            u1 = fma2(xb, pk2(wC.z, wC.w), u1);
            u2 = fma2(xb, pk2(wD.x, wD.y), u2);
            u3 = fma2(xb, pk2(wD.z, wD.w), u3);
        }

        su0 = add2(su0, u0); su1 = add2(su1, u1);
        su2 = add2(su2, u2); su3 = add2(su3, u3);

        // argmax over classes (first-max semantics)
        float best;
        int   wbest = 0;
        {
            unsigned long long acc = mul2(u0, rdc[0]);
            acc = fma2(u1, rdc[1], acc);
            acc = fma2(u2, rdc[2], acc);
            acc = fma2(u3, rdc[3], acc);
            float2 t = upk2(acc);
            best = t.x + t.y;
        }
        #pragma unroll
        for (int c = 1; c < Cc; c++) {
            unsigned long long acc = mul2(u0, rdc[4 * c]);
            acc = fma2(u1, rdc[4 * c + 1], acc);
            acc = fma2(u2, rdc[4 * c + 2], acc);
            acc = fma2(u3, rdc[4 * c + 3], acc);
            float2 t = upk2(acc);
            float  s = t.x + t.y;
            if (s > best) { best = s; wbest = c; }
        }

        // per-thread-private bf16x2 segment accumulation (bank = tid%32)
        unsigned v0 = cvt_bf16x2(u0), v1 = cvt_bf16x2(u1);
        unsigned v2 = cvt_bf16x2(u2), v3 = cvt_bf16x2(u3);
        unsigned* segp = sSeg + wbest * 4 * 256 + tid;
        {
            unsigned o;
            __nv_bfloat162 r;
            o = segp[0];
            r = __hadd2(*(__nv_bfloat162*)&o, *(__nv_bfloat162*)&v0);
            segp[0] = *(unsigned*)&r;
            o = segp[256];
            r = __hadd2(*(__nv_bfloat162*)&o, *(__nv_bfloat162*)&v1);
            segp[256] = *(unsigned*)&r;
            o = segp[512];
            r = __hadd2(*(__nv_bfloat162*)&o, *(__nv_bfloat162*)&v2);
            segp[512] = *(unsigned*)&r;
            o = segp[768];
            r = __hadd2(*(__nv_bfloat162*)&o, *(__nv_bfloat162*)&v3);
            segp[768] = *(unsigned*)&r;
            // count: bf16 1.0 into the (wbest&1) half
            unsigned inc = (wbest & 1) ? 0x3F800000u : 0x00003F80u;
            unsigned* cp = sSeg + (40 + (wbest >> 1)) * 256 + tid;
            o = *cp;
            r = __hadd2(*(__nv_bfloat162*)&o, *(__nv_bfloat162*)&inc);
            *cp = *(unsigned*)&r;
        }
    }

    // ---- sum_u: reduce over the 8 threads sharing b ----
    #pragma unroll
    for (int d = 1; d < 8; d <<= 1) {
        su0 = add2(su0, __shfl_xor_sync(0xffffffffu, su0, d));
        su1 = add2(su1, __shfl_xor_sync(0xffffffffu, su1, d));
        su2 = add2(su2, __shfl_xor_sync(0xffffffffu, su2, d));
        su3 = add2(su3, __shfl_xor_sync(0xffffffffu, su3, d));
    }
    if (sub == 0) {
        float2 t;
        t = upk2(su0); atomicAdd(&g_scratch[b * 8 + 0], t.x); atomicAdd(&g_scratch[b * 8 + 1], t.y);
        t = upk2(su1); atomicAdd(&g_scratch[b * 8 + 2], t.x); atomicAdd(&g_scratch[b * 8 + 3], t.y);
        t = upk2(su2); atomicAdd(&g_scratch[b * 8 + 4], t.x); atomicAdd(&g_scratch[b * 8 + 5], t.y);
        t = upk2(su3); atomicAdd(&g_scratch[b * 8 + 6], t.x); atomicAdd(&g_scratch[b * 8 + 7], t.y);
    }

    __syncthreads();

    // ---- reduce the 45 private-pair slots; warp per slot, conflict-free ----
    const int warp = tid >> 5;
    const int lane = tid & 31;
    for (int slot = warp; slot < NPAIR; slot += 8) {
        const unsigned* base = sSeg + slot * 256;
        float sx = 0.0f, sy = 0.0f;
        #pragma unroll
        for (int k = 0; k < 8; k++) {
            unsigned v = base[k * 32 + lane];
            float2 f = __bfloat1622float2(*(__nv_bfloat162*)&v);
            sx += f.x; sy += f.y;
        }
        #pragma unroll
        for (int d = 16; d > 0; d >>= 1) {
            sx += __shfl_xor_sync(0xffffffffu, sx, d);
            sy += __shfl_xor_sync(0xffffffffu, sy, d);
        }
        if (lane == 0) {
            int g0;
            if (slot < 40) {
                int c = slot >> 2, dp = slot & 3;
                g0 = 1024 + c * 8 + 2 * dp;
            } else {
                g0 = 1104 + 2 * (slot - 40);
            }
            atomicAdd(&g_scratch[g0], sx);
            atomicAdd(&g_scratch[g0 + 1], sy);
        }
    }
}

__global__ void caps_final_kernel(const float* __restrict__ dcg,
                                  float* __restrict__ out)
{
    __shared__ float s_sum[Bsz * Dd];
    __shared__ float dcn[Cc * Dd];
    const int tid = threadIdx.x;   // 256 threads, 1 block

    for (int i = tid; i < Bsz * Dd; i += 256) s_sum[i] = g_scratch[i];

    if (tid < Cc * Dd) {
        int   c   = tid >> 3;
        float v   = dcg[tid];
        float upd = (g_scratch[1024 + tid] - g_scratch[1104 + c] * v)
                    * (1.0f / (float)(Bsz * Ntot));
        float nv  = v + upd;
        dcn[tid] = nv;
        out[Bsz * Cc + tid] = nv;          // digit_caps_new tail
    }
    __syncthreads();

    // self-clean scratch for the next graph replay
    for (int i = tid; i < 1120; i += 256) g_scratch[i] = 0.0f;

    for (int idx = tid; idx < Bsz * Cc; idx += 256) {
        int b = idx / Cc;
        int c = idx - b * Cc;
        float s = 0.0f;
        #pragma unroll
        for (int d = 0; d < Dd; d++) s += s_sum[b * 8 + d] * dcn[c * 8 + d];
        out[idx] = s * (1.0f / (float)Ntot);
    }
}

extern "C" void kernel_launch(void* const* d_in, const int* in_sizes, int n_in,
                              void* d_out, int out_size)
{
    const float* xin = (const float*)d_in[0];  // inputs [128,12,12,32,8]
    const float* Wg  = (const float*)d_in[1];  // W [4608,8,32]
    const float* dcg = (const float*)d_in[2];  // digit_caps [10,8]
    float* out = (float*)d_out;

    size_t smemBytes = (size_t)(JB * WSTR + BB * XSTR + NPAIR * 256) * sizeof(float);
    cudaFuncSetAttribute(caps_main_kernel,
                         cudaFuncAttributeMaxDynamicSharedMemorySize,
                         (int)smemBytes);
    dim3 grid(Jtot / JB, Bsz / BB);
    caps_main_kernel<<<grid, NTHR, smemBytes>>>(xin, Wg, dcg);

    caps_final_kernel<<<1, 256>>>(dcg, out);
}